// round 8
// baseline (speedup 1.0000x reference)
#include <cuda_runtime.h>
#include <cstdint>
#include <cstddef>

#define BN 16
#define HH 512
#define WW 512
#define NPIX (BN*HH*WW)          // 4194304
#define CNUM 6
#define LNUM 3

// ---------------- static device scratch (no allocations allowed) ----------------
__device__ float    g_img[NPIX];                     // normalized working image (16MB)
__device__ float    g_cvals[NPIX];                   // per-class staged c values (16MB)
__device__ unsigned g_list[(size_t)CNUM * NPIX];     // per-class pixel lists (100MB)
__device__ unsigned g_cnt[CNUM];
__device__ unsigned g_mnu[BN], g_mxu[BN];            // order-encoded min/max bits
__device__ float    g_tbl[BN * CNUM * 128];          // per (b,cls): 25*float4 weights,
                                                     // float4 biases, 3*float4 bezier params

// ---------------- helpers ----------------
__device__ __forceinline__ unsigned fenc(float f) {
    unsigned b = __float_as_uint(f);
    return (b & 0x80000000u) ? ~b : (b | 0x80000000u);
}
__device__ __forceinline__ float fdec(unsigned u) {
    unsigned b = (u & 0x80000000u) ? (u ^ 0x80000000u) : ~u;
    return __uint_as_float(b);
}
__device__ __forceinline__ float sigm(float x) { return 1.0f / (1.0f + __expf(-x)); }

__device__ __forceinline__ float bez(float c, float mix,
                                     float p1, float p2, float p1v, float p2v) {
    float om  = 1.0f - c;
    float om2 = om * om, c2 = c * c;
    float ct = 3.0f * om2 * c * p1 + 3.0f * om * c2 * p2 + c2 * c;
    float cv = om2 * om + 3.0f * om2 * c * p1v + 3.0f * om * c2 * p2v;
    float v  = ct * mix + cv * (1.0f - mix);
    return fminf(fmaxf(v, 0.0f), 1.0f);
}

// ---------------- kernels ----------------
__global__ void k_init() {
    int t = threadIdx.x;
    if (t < CNUM) g_cnt[t] = 0u;
    if (t < BN) { g_mnu[t] = 0xFFFFFFFFu; g_mxu[t] = 0u; }
}

// per-sample min/max: 8 blocks per sample, float4 loads, encoded atomics
__global__ void k_minmax(const float4* __restrict__ x) {
    int b = blockIdx.x >> 3, chunk = blockIdx.x & 7;
    const float4* p = x + (size_t)b * 65536 + (size_t)chunk * 8192;
    float mn = 3.4e38f, mx = -3.4e38f;
    for (int i = threadIdx.x; i < 8192; i += 256) {
        float4 v = __ldg(p + i);
        mn = fminf(mn, fminf(fminf(v.x, v.y), fminf(v.z, v.w)));
        mx = fmaxf(mx, fmaxf(fmaxf(v.x, v.y), fmaxf(v.z, v.w)));
    }
    for (int o = 16; o; o >>= 1) {
        mn = fminf(mn, __shfl_down_sync(0xffffffffu, mn, o));
        mx = fmaxf(mx, __shfl_down_sync(0xffffffffu, mx, o));
    }
    __shared__ float smn[8], smx[8];
    if ((threadIdx.x & 31) == 0) { smn[threadIdx.x >> 5] = mn; smx[threadIdx.x >> 5] = mx; }
    __syncthreads();
    if (threadIdx.x == 0) {
        for (int w = 1; w < 8; w++) { mn = fminf(mn, smn[w]); mx = fmaxf(mx, smx[w]); }
        atomicMin(&g_mnu[b], fenc(mn));
        atomicMax(&g_mxu[b], fenc(mx));
    }
}

// normalize into working image (float4)
__global__ void k_norm(const float4* __restrict__ x) {
    unsigned i = blockIdx.x * 256u + threadIdx.x;     // float4 index
    int b = i >> 16;                                   // (i*4)>>18
    float mn  = fdec(g_mnu[b]);
    float inv = 1.0f / (fdec(g_mxu[b]) - mn + 1e-8f);
    float4 v = __ldg(x + i);
    float4 o = make_float4((v.x - mn) * inv, (v.y - mn) * inv,
                           (v.z - mn) * inv, (v.w - mn) * inv);
    reinterpret_cast<float4*>(g_img)[i] = o;
}

// build compacted per-class pixel lists. Block = 16384 consecutive pixels
// (keeps each list chunk spatially local & single-sample), ballot-aggregated.
__global__ void k_build(const int* __restrict__ lbl) {
    __shared__ unsigned sbase[CNUM];
    __shared__ unsigned scur[CNUM];
    const int t = threadIdx.x;
    const int lane = t & 31;
    const unsigned base = blockIdx.x * 16384u;

    // pass 1: per-thread counts (register accumulators, no indexing)
    unsigned c0 = 0, c1 = 0, c2 = 0, c3 = 0, c4 = 0, c5 = 0;
    for (int s = 0; s < 64; s++) {
        int c = lbl[base + (unsigned)s * 256u + t];
        c0 += (c == 0); c1 += (c == 1); c2 += (c == 2);
        c3 += (c == 3); c4 += (c == 4); c5 += (c == 5);
    }
    if (t < CNUM) scur[t] = 0u;
    __syncthreads();
    for (int o = 16; o; o >>= 1) {
        c0 += __shfl_down_sync(0xffffffffu, c0, o);
        c1 += __shfl_down_sync(0xffffffffu, c1, o);
        c2 += __shfl_down_sync(0xffffffffu, c2, o);
        c3 += __shfl_down_sync(0xffffffffu, c3, o);
        c4 += __shfl_down_sync(0xffffffffu, c4, o);
        c5 += __shfl_down_sync(0xffffffffu, c5, o);
    }
    if (lane == 0) {
        atomicAdd(&scur[0], c0); atomicAdd(&scur[1], c1); atomicAdd(&scur[2], c2);
        atomicAdd(&scur[3], c3); atomicAdd(&scur[4], c4); atomicAdd(&scur[5], c5);
    }
    __syncthreads();
    if (t < CNUM) sbase[t] = atomicAdd(&g_cnt[t], scur[t]);
    __syncthreads();
    if (t < CNUM) scur[t] = 0u;
    __syncthreads();

    // pass 2: emit (warp-aggregated, coalesced list writes)
    for (int s = 0; s < 64; s++) {
        unsigned p = base + (unsigned)s * 256u + t;
        int myc = lbl[p];
#pragma unroll
        for (int c = 0; c < CNUM; c++) {
            unsigned m = __ballot_sync(0xffffffffu, myc == c);
            if (!m) continue;
            int ldr = __ffs(m) - 1;
            unsigned wb = 0;
            if (lane == ldr) wb = atomicAdd(&scur[c], (unsigned)__popc(m));
            wb = __shfl_sync(0xffffffffu, wb, ldr);
            if (myc == c) {
                unsigned slot = wb + (unsigned)__popc(m & ((1u << lane) - 1u));
                g_list[(size_t)c * NPIX + sbase[c] + slot] = p;
            }
        }
    }
}

// precompute effective 5x5 kernels + biases + sigmoided Bezier params.
// One thread per (sample, class, layer) = 288 threads.
__global__ void k_tbl(const int* __restrict__ index, const float* __restrict__ param,
                      const float* __restrict__ w1, const float* __restrict__ b1,
                      const float* __restrict__ w2, const float* __restrict__ b2) {
    int t = blockIdx.x * blockDim.x + threadIdx.x;
    if (t >= BN * CNUM * LNUM) return;
    int b = t / (CNUM * LNUM);
    int i = (t / LNUM) % CNUM;
    int l = t % LNUM;
    int d = __ldg(index + b);
    int k = ((d * CNUM + i) * 4) * LNUM + l;   // aug index fixed to 0
    const float* W1 = w1 + (size_t)k * 36;     // [4][3][3]
    const float* W2 = w2 + (size_t)k * 36;     // [1][4][3][3]
    const float* B1 = b1 + (size_t)k * 4;
    const float* P  = param + (size_t)k * 7;

    float wef[25];
#pragma unroll
    for (int j = 0; j < 25; j++) wef[j] = 0.0f;
    float beff = __ldg(b2 + k);
#pragma unroll
    for (int ch = 0; ch < 4; ch++) {
        float s2 = 0.0f;
#pragma unroll
        for (int e = 0; e < 9; e++) {
            float w2v = __ldg(W2 + ch * 9 + e);
            s2 += w2v;
            int ey = e / 3, ex = e % 3;
#pragma unroll
            for (int dd = 0; dd < 9; dd++) {
                wef[(ey + dd / 3) * 5 + (ex + dd % 3)] += w2v * __ldg(W1 + ch * 9 + dd);
            }
        }
        beff += __ldg(B1 + ch) * s2;
    }
    float* T = g_tbl + (size_t)(b * CNUM + i) * 128;
#pragma unroll
    for (int j = 0; j < 25; j++) T[j * 4 + l] = wef[j];
    T[100 + l] = beff;
#pragma unroll
    for (int j = 0; j < 4; j++) T[104 + l * 4 + j] = sigm(__ldg(P + j));
    if (l == 0) {
        T[103] = 0.0f;
#pragma unroll
        for (int j = 0; j < 25; j++) T[j * 4 + 3] = 0.0f;
    }
}

// per-class compute: one thread per masked pixel (from compacted list).
// Interior pixels: composed 5x5 conv x3 layers. Border ring: exact two-step conv.
__global__ void __launch_bounds__(256) k_compute(int cls,
        const int* __restrict__ index,
        const float* __restrict__ w1, const float* __restrict__ b1,
        const float* __restrict__ w2, const float* __restrict__ b2) {
    unsigned cnt = g_cnt[cls];
    const unsigned* __restrict__ list = g_list + (size_t)cls * NPIX;
    unsigned stride = gridDim.x * blockDim.x;
    for (unsigned j = blockIdx.x * blockDim.x + threadIdx.x; j < cnt; j += stride) {
        unsigned p = list[j];
        int b = p >> 18;
        int y = (p >> 9) & 511;
        int x = p & 511;

        float nb[25];
        if (y >= 2 && y < HH - 2 && x >= 2 && x < WW - 2) {
            const float* q = g_img + p - 2 * WW - 2;
#pragma unroll
            for (int r = 0; r < 5; r++)
#pragma unroll
                for (int cix = 0; cix < 5; cix++)
                    nb[r * 5 + cix] = __ldg(q + r * WW + cix);
        } else {
            const float* base = g_img + ((size_t)b << 18);
#pragma unroll
            for (int r = 0; r < 5; r++)
#pragma unroll
                for (int cix = 0; cix < 5; cix++) {
                    int yy = y + r - 2, xx = x + cix - 2;
                    nb[r * 5 + cix] = (yy >= 0 && yy < HH && xx >= 0 && xx < WW)
                                      ? __ldg(base + yy * WW + xx) : 0.0f;
                }
        }

        const float4* T4 = reinterpret_cast<const float4*>(g_tbl)
                           + (size_t)(b * CNUM + cls) * 32;
        float cc = nb[12];  // c = xn * mask, mask true at this pixel

        if (y >= 1 && y < HH - 1 && x >= 1 && x < WW - 1) {
            float4 bb = __ldg(T4 + 25);
            float a0 = bb.x, a1 = bb.y, a2 = bb.z;
#pragma unroll
            for (int t = 0; t < 25; t++) {
                float4 w = __ldg(T4 + t);
                float v = nb[t];
                a0 += v * w.x; a1 += v * w.y; a2 += v * w.z;
            }
            float4 pA = __ldg(T4 + 26), pB = __ldg(T4 + 27), pC = __ldg(T4 + 28);
            cc = bez(cc, sigm(a0), pA.x, pA.y, pA.z, pA.w);
            cc = bez(cc, sigm(a1), pB.x, pB.y, pB.z, pB.w);
            cc = bez(cc, sigm(a2), pC.x, pC.y, pC.z, pC.w);
        } else {
            // exact path: intermediate h is zero-padded (not composed) at borders
            int d = __ldg(index + b);
            int kb = ((d * CNUM + cls) * 4) * LNUM;
#pragma unroll
            for (int l = 0; l < LNUM; l++) {
                int k = kb + l;
                const float* W1 = w1 + (size_t)k * 36;
                const float* W2 = w2 + (size_t)k * 36;
                const float* B1 = b1 + (size_t)k * 4;
                float acc = __ldg(b2 + k);
#pragma unroll
                for (int e = 0; e < 9; e++) {
                    int ey = e / 3 - 1, ex = e % 3 - 1;
                    int qy = y + ey, qx = x + ex;
                    if (qy < 0 || qy >= HH || qx < 0 || qx >= WW) continue;
                    float hs = 0.0f;
#pragma unroll
                    for (int ch = 0; ch < 4; ch++) {
                        float h = __ldg(B1 + ch);
#pragma unroll
                        for (int dd = 0; dd < 9; dd++) {
                            int dy = dd / 3 - 1, dx = dd % 3 - 1;
                            h += __ldg(W1 + ch * 9 + dd) * nb[(2 + ey + dy) * 5 + (2 + ex + dx)];
                        }
                        hs += h * __ldg(W2 + ch * 9 + e);
                    }
                    acc += hs;
                }
                float4 pp = __ldg(T4 + 26 + l);
                cc = bez(cc, sigm(acc), pp.x, pp.y, pp.z, pp.w);
            }
        }
        g_cvals[j] = cc;
    }
}

// scatter staged values into image (safe: separate launch = grid-wide sync)
__global__ void k_scatter(int cls) {
    unsigned cnt = g_cnt[cls];
    const unsigned* __restrict__ list = g_list + (size_t)cls * NPIX;
    unsigned stride = gridDim.x * blockDim.x;
    for (unsigned j = blockIdx.x * blockDim.x + threadIdx.x; j < cnt; j += stride)
        g_img[list[j]] = g_cvals[j];
}

// denormalize into output
__global__ void k_final(float4* __restrict__ out) {
    unsigned i = blockIdx.x * 256u + threadIdx.x;  // float4 index
    int b = i >> 16;
    float mn = fdec(g_mnu[b]);
    float sc = fdec(g_mxu[b]) - mn + 1e-8f;
    float4 v = reinterpret_cast<const float4*>(g_img)[i];
    out[i] = make_float4(v.x * sc + mn, v.y * sc + mn, v.z * sc + mn, v.w * sc + mn);
}

// ---------------- launch ----------------
extern "C" void kernel_launch(void* const* d_in, const int* in_sizes, int n_in,
                              void* d_out, int out_size) {
    const float* x     = (const float*)d_in[0];
    const int*   lbl   = (const int*)d_in[1];
    const int*   index = (const int*)d_in[2];
    const float* param = (const float*)d_in[3];
    const float* w1    = (const float*)d_in[4];
    const float* b1    = (const float*)d_in[5];
    const float* w2    = (const float*)d_in[6];
    const float* b2    = (const float*)d_in[7];

    k_init<<<1, 64>>>();
    k_minmax<<<BN * 8, 256>>>((const float4*)x);
    k_norm<<<NPIX / 1024, 256>>>((const float4*)x);
    k_build<<<NPIX / 16384, 256>>>(lbl);
    k_tbl<<<1, 288>>>(index, param, w1, b1, w2, b2);
    for (int c = 0; c < CNUM; c++) {
        k_compute<<<1184, 256>>>(c, index, w1, b1, w2, b2);
        k_scatter<<<1184, 256>>>(c);
    }
    k_final<<<NPIX / 1024, 256>>>((float4*)d_out);
}

// round 9
// speedup vs baseline: 1.1948x; 1.1948x over previous
#include <cuda_runtime.h>
#include <cstdint>
#include <cstddef>

#define BN 16
#define HH 512
#define WW 512
#define NPIX (BN*HH*WW)          // 4194304
#define CNUM 6
#define LNUM 3

// ---------------- static device scratch (no allocations allowed) ----------------
__device__ float    g_img[NPIX];                     // normalized working image (16MB)
__device__ float    g_cvals[NPIX];                   // per-class staged c values (16MB)
__device__ unsigned g_list[(size_t)CNUM * NPIX];     // per-class pixel lists (100MB)
__device__ unsigned g_cnt[CNUM];
__device__ unsigned g_mnu[BN], g_mxu[BN];            // order-encoded min/max bits
__device__ float    g_tbl[BN * CNUM * 128];          // per (b,cls): 25*float4 weights,
                                                     // float4 biases, 3*float4 bezier params

// ---------------- helpers ----------------
__device__ __forceinline__ unsigned fenc(float f) {
    unsigned b = __float_as_uint(f);
    return (b & 0x80000000u) ? ~b : (b | 0x80000000u);
}
__device__ __forceinline__ float fdec(unsigned u) {
    unsigned b = (u & 0x80000000u) ? (u ^ 0x80000000u) : ~u;
    return __uint_as_float(b);
}
__device__ __forceinline__ float sigm(float x) { return 1.0f / (1.0f + __expf(-x)); }

__device__ __forceinline__ float bez(float c, float mix,
                                     float p1, float p2, float p1v, float p2v) {
    float om  = 1.0f - c;
    float om2 = om * om, c2 = c * c;
    float ct = 3.0f * om2 * c * p1 + 3.0f * om * c2 * p2 + c2 * c;
    float cv = om2 * om + 3.0f * om2 * c * p1v + 3.0f * om * c2 * p2v;
    float v  = ct * mix + cv * (1.0f - mix);
    return fminf(fmaxf(v, 0.0f), 1.0f);
}

// ---------------- setup: counters/minmax init + effective 5x5 table ----------------
// One block, 288 threads: thread t handles (sample,class,layer) + init duties.
__global__ void k_setup(const int* __restrict__ index, const float* __restrict__ param,
                        const float* __restrict__ w1, const float* __restrict__ b1,
                        const float* __restrict__ w2, const float* __restrict__ b2) {
    int t = threadIdx.x;
    if (t < CNUM) g_cnt[t] = 0u;
    if (t < BN) { g_mnu[t] = 0xFFFFFFFFu; g_mxu[t] = 0u; }
    if (t >= BN * CNUM * LNUM) return;
    int b = t / (CNUM * LNUM);
    int i = (t / LNUM) % CNUM;
    int l = t % LNUM;
    int d = __ldg(index + b);
    int k = ((d * CNUM + i) * 4) * LNUM + l;   // aug index fixed to 0
    const float* W1 = w1 + (size_t)k * 36;     // [4][3][3]
    const float* W2 = w2 + (size_t)k * 36;     // [1][4][3][3]
    const float* B1 = b1 + (size_t)k * 4;
    const float* P  = param + (size_t)k * 7;

    float wef[25];
#pragma unroll
    for (int j = 0; j < 25; j++) wef[j] = 0.0f;
    float beff = __ldg(b2 + k);
#pragma unroll
    for (int ch = 0; ch < 4; ch++) {
        float s2 = 0.0f;
#pragma unroll
        for (int e = 0; e < 9; e++) {
            float w2v = __ldg(W2 + ch * 9 + e);
            s2 += w2v;
            int ey = e / 3, ex = e % 3;
#pragma unroll
            for (int dd = 0; dd < 9; dd++) {
                wef[(ey + dd / 3) * 5 + (ex + dd % 3)] += w2v * __ldg(W1 + ch * 9 + dd);
            }
        }
        beff += __ldg(B1 + ch) * s2;
    }
    float* T = g_tbl + (size_t)(b * CNUM + i) * 128;
#pragma unroll
    for (int j = 0; j < 25; j++) T[j * 4 + l] = wef[j];
    T[100 + l] = beff;
#pragma unroll
    for (int j = 0; j < 4; j++) T[104 + l * 4 + j] = sigm(__ldg(P + j));
    if (l == 0) {
        T[103] = 0.0f;
#pragma unroll
        for (int j = 0; j < 25; j++) T[j * 4 + 3] = 0.0f;
    }
}

// per-sample min/max: 8 blocks per sample, float4 loads, encoded atomics
__global__ void k_minmax(const float4* __restrict__ x) {
    int b = blockIdx.x >> 3, chunk = blockIdx.x & 7;
    const float4* p = x + (size_t)b * 65536 + (size_t)chunk * 8192;
    float mn = 3.4e38f, mx = -3.4e38f;
    for (int i = threadIdx.x; i < 8192; i += 256) {
        float4 v = __ldg(p + i);
        mn = fminf(mn, fminf(fminf(v.x, v.y), fminf(v.z, v.w)));
        mx = fmaxf(mx, fmaxf(fmaxf(v.x, v.y), fmaxf(v.z, v.w)));
    }
    for (int o = 16; o; o >>= 1) {
        mn = fminf(mn, __shfl_down_sync(0xffffffffu, mn, o));
        mx = fmaxf(mx, __shfl_down_sync(0xffffffffu, mx, o));
    }
    __shared__ float smn[8], smx[8];
    if ((threadIdx.x & 31) == 0) { smn[threadIdx.x >> 5] = mn; smx[threadIdx.x >> 5] = mx; }
    __syncthreads();
    if (threadIdx.x == 0) {
        for (int w = 1; w < 8; w++) { mn = fminf(mn, smn[w]); mx = fmaxf(mx, smx[w]); }
        atomicMin(&g_mnu[b], fenc(mn));
        atomicMax(&g_mxu[b], fenc(mx));
    }
}

// Fused normalize + per-class list build.
// 2048 blocks x 256 threads; each block owns 2048 consecutive pixels (one sample).
// Warp-range reservation: one shared atomic per class per warp, then atomic-free
// ballot/popc emission (no shfl, no ATOMS in the emit loop).
__global__ void __launch_bounds__(256) k_build(const float4* __restrict__ x,
                                               const int* __restrict__ lbl) {
    __shared__ unsigned scur[CNUM];    // running within-block offsets
    __shared__ unsigned sbase[CNUM];   // block base within global list
    const int t = threadIdx.x;
    const int lane = t & 31;
    const unsigned base = blockIdx.x * 2048u;
    const int b = base >> 18;

    // --- fused normalization: 2 float4 per thread ---
    {
        float mn  = fdec(g_mnu[b]);
        float inv = 1.0f / (fdec(g_mxu[b]) - mn + 1e-8f);
        unsigned f4 = (base >> 2) + t;
#pragma unroll
        for (int s = 0; s < 2; s++) {
            float4 v = __ldg(x + f4 + s * 256);
            reinterpret_cast<float4*>(g_img)[f4 + s * 256] =
                make_float4((v.x - mn) * inv, (v.y - mn) * inv,
                            (v.z - mn) * inv, (v.w - mn) * inv);
        }
    }

    if (t < CNUM) scur[t] = 0u;
    __syncthreads();

    // --- pass A: per-thread counts, labels stashed in registers ---
    int lc[8];
    unsigned c0 = 0, c1 = 0, c2 = 0, c3 = 0, c4 = 0, c5 = 0;
#pragma unroll
    for (int s = 0; s < 8; s++) {
        int c = __ldg(lbl + base + (unsigned)s * 256u + t);
        lc[s] = c;
        c0 += (c == 0); c1 += (c == 1); c2 += (c == 2);
        c3 += (c == 3); c4 += (c == 4); c5 += (c == 5);
    }
#pragma unroll
    for (int o = 16; o; o >>= 1) {
        c0 += __shfl_down_sync(0xffffffffu, c0, o);
        c1 += __shfl_down_sync(0xffffffffu, c1, o);
        c2 += __shfl_down_sync(0xffffffffu, c2, o);
        c3 += __shfl_down_sync(0xffffffffu, c3, o);
        c4 += __shfl_down_sync(0xffffffffu, c4, o);
        c5 += __shfl_down_sync(0xffffffffu, c5, o);
    }
    // warp leader reserves per-class ranges within the block
    unsigned w0 = 0, w1o = 0, w2o = 0, w3o = 0, w4o = 0, w5o = 0;
    if (lane == 0) {
        w0  = atomicAdd(&scur[0], c0); w1o = atomicAdd(&scur[1], c1);
        w2o = atomicAdd(&scur[2], c2); w3o = atomicAdd(&scur[3], c3);
        w4o = atomicAdd(&scur[4], c4); w5o = atomicAdd(&scur[5], c5);
    }
    __syncthreads();
    if (t < CNUM) sbase[t] = atomicAdd(&g_cnt[t], scur[t]);
    __syncthreads();
    // broadcast warp offsets; add block base -> per-warp running cursors (uniform across lanes)
    unsigned r0 = sbase[0] + __shfl_sync(0xffffffffu, w0, 0);
    unsigned r1 = sbase[1] + __shfl_sync(0xffffffffu, w1o, 0);
    unsigned r2 = sbase[2] + __shfl_sync(0xffffffffu, w2o, 0);
    unsigned r3 = sbase[3] + __shfl_sync(0xffffffffu, w3o, 0);
    unsigned r4 = sbase[4] + __shfl_sync(0xffffffffu, w4o, 0);
    unsigned r5 = sbase[5] + __shfl_sync(0xffffffffu, w5o, 0);
    const unsigned lmask = (1u << lane) - 1u;

    // --- pass B: atomic-free emit ---
#pragma unroll
    for (int s = 0; s < 8; s++) {
        unsigned p = base + (unsigned)s * 256u + t;
        int myc = lc[s];
        unsigned m;
        m = __ballot_sync(0xffffffffu, myc == 0);
        if (myc == 0) g_list[0 * (size_t)NPIX + r0 + __popc(m & lmask)] = p;
        r0 += __popc(m);
        m = __ballot_sync(0xffffffffu, myc == 1);
        if (myc == 1) g_list[1 * (size_t)NPIX + r1 + __popc(m & lmask)] = p;
        r1 += __popc(m);
        m = __ballot_sync(0xffffffffu, myc == 2);
        if (myc == 2) g_list[2 * (size_t)NPIX + r2 + __popc(m & lmask)] = p;
        r2 += __popc(m);
        m = __ballot_sync(0xffffffffu, myc == 3);
        if (myc == 3) g_list[3 * (size_t)NPIX + r3 + __popc(m & lmask)] = p;
        r3 += __popc(m);
        m = __ballot_sync(0xffffffffu, myc == 4);
        if (myc == 4) g_list[4 * (size_t)NPIX + r4 + __popc(m & lmask)] = p;
        r4 += __popc(m);
        m = __ballot_sync(0xffffffffu, myc == 5);
        if (myc == 5) g_list[5 * (size_t)NPIX + r5 + __popc(m & lmask)] = p;
        r5 += __popc(m);
    }
}

// per-class compute: one thread per masked pixel (from compacted list).
// Weight/param tables for all 16 samples of this class cached in shared memory.
// Interior pixels: composed 5x5 conv x3 layers. Border ring: exact two-step conv.
__global__ void __launch_bounds__(256) k_compute(int cls,
        const int* __restrict__ index,
        const float* __restrict__ w1, const float* __restrict__ b1,
        const float* __restrict__ w2, const float* __restrict__ b2) {
    __shared__ float4 sT[BN * 32];   // 8KB
    {
        const float4* gT = reinterpret_cast<const float4*>(g_tbl);
#pragma unroll
        for (int s = 0; s < 2; s++) {
            int i = threadIdx.x + s * 256;
            int bb = i >> 5, e = i & 31;
            sT[i] = __ldg(gT + (size_t)(bb * CNUM + cls) * 32 + e);
        }
    }
    __syncthreads();

    unsigned cnt = g_cnt[cls];
    const unsigned* __restrict__ list = g_list + (size_t)cls * NPIX;
    unsigned stride = gridDim.x * blockDim.x;
    for (unsigned j = blockIdx.x * blockDim.x + threadIdx.x; j < cnt; j += stride) {
        unsigned p = __ldg(list + j);
        int b = p >> 18;
        int y = (p >> 9) & 511;
        int x = p & 511;

        float nb[25];
        if (y >= 2 && y < HH - 2 && x >= 2 && x < WW - 2) {
            const float* q = g_img + p - 2 * WW - 2;
#pragma unroll
            for (int r = 0; r < 5; r++)
#pragma unroll
                for (int cix = 0; cix < 5; cix++)
                    nb[r * 5 + cix] = __ldg(q + r * WW + cix);
        } else {
            const float* basep = g_img + ((size_t)b << 18);
#pragma unroll
            for (int r = 0; r < 5; r++)
#pragma unroll
                for (int cix = 0; cix < 5; cix++) {
                    int yy = y + r - 2, xx = x + cix - 2;
                    nb[r * 5 + cix] = (yy >= 0 && yy < HH && xx >= 0 && xx < WW)
                                      ? __ldg(basep + yy * WW + xx) : 0.0f;
                }
        }

        const float4* T4 = sT + (b << 5);
        float cc = nb[12];  // c = xn * mask, mask true at this pixel

        if (y >= 1 && y < HH - 1 && x >= 1 && x < WW - 1) {
            float4 bb4 = T4[25];
            float a0 = bb4.x, a1 = bb4.y, a2 = bb4.z;
#pragma unroll
            for (int t = 0; t < 25; t++) {
                float4 w = T4[t];
                float v = nb[t];
                a0 += v * w.x; a1 += v * w.y; a2 += v * w.z;
            }
            float4 pA = T4[26], pB = T4[27], pC = T4[28];
            cc = bez(cc, sigm(a0), pA.x, pA.y, pA.z, pA.w);
            cc = bez(cc, sigm(a1), pB.x, pB.y, pB.z, pB.w);
            cc = bez(cc, sigm(a2), pC.x, pC.y, pC.z, pC.w);
        } else {
            // exact path: intermediate h is zero-padded (not composed) at borders
            int d = __ldg(index + b);
            int kb = ((d * CNUM + cls) * 4) * LNUM;
#pragma unroll
            for (int l = 0; l < LNUM; l++) {
                int k = kb + l;
                const float* W1 = w1 + (size_t)k * 36;
                const float* W2 = w2 + (size_t)k * 36;
                const float* B1 = b1 + (size_t)k * 4;
                float acc = __ldg(b2 + k);
#pragma unroll
                for (int e = 0; e < 9; e++) {
                    int ey = e / 3 - 1, ex = e % 3 - 1;
                    int qy = y + ey, qx = x + ex;
                    if (qy < 0 || qy >= HH || qx < 0 || qx >= WW) continue;
                    float hs = 0.0f;
#pragma unroll
                    for (int ch = 0; ch < 4; ch++) {
                        float h = __ldg(B1 + ch);
#pragma unroll
                        for (int dd = 0; dd < 9; dd++) {
                            int dy = dd / 3 - 1, dx = dd % 3 - 1;
                            h += __ldg(W1 + ch * 9 + dd) * nb[(2 + ey + dy) * 5 + (2 + ex + dx)];
                        }
                        hs += h * __ldg(W2 + ch * 9 + e);
                    }
                    acc += hs;
                }
                float4 pp = T4[26 + l];
                cc = bez(cc, sigm(acc), pp.x, pp.y, pp.z, pp.w);
            }
        }
        g_cvals[j] = cc;
    }
}

// scatter staged values into image (safe: separate launch = grid-wide sync)
__global__ void k_scatter(int cls) {
    unsigned cnt = g_cnt[cls];
    const unsigned* __restrict__ list = g_list + (size_t)cls * NPIX;
    unsigned stride = gridDim.x * blockDim.x;
    for (unsigned j = blockIdx.x * blockDim.x + threadIdx.x; j < cnt; j += stride)
        g_img[__ldg(list + j)] = __ldg(g_cvals + j);
}

// denormalize into output
__global__ void k_final(float4* __restrict__ out) {
    unsigned i = blockIdx.x * 256u + threadIdx.x;  // float4 index
    int b = i >> 16;
    float mn = fdec(g_mnu[b]);
    float sc = fdec(g_mxu[b]) - mn + 1e-8f;
    float4 v = reinterpret_cast<const float4*>(g_img)[i];
    out[i] = make_float4(v.x * sc + mn, v.y * sc + mn, v.z * sc + mn, v.w * sc + mn);
}

// ---------------- launch ----------------
extern "C" void kernel_launch(void* const* d_in, const int* in_sizes, int n_in,
                              void* d_out, int out_size) {
    const float* x     = (const float*)d_in[0];
    const int*   lbl   = (const int*)d_in[1];
    const int*   index = (const int*)d_in[2];
    const float* param = (const float*)d_in[3];
    const float* w1    = (const float*)d_in[4];
    const float* b1    = (const float*)d_in[5];
    const float* w2    = (const float*)d_in[6];
    const float* b2    = (const float*)d_in[7];

    k_setup<<<1, 288>>>(index, param, w1, b1, w2, b2);
    k_minmax<<<BN * 8, 256>>>((const float4*)x);
    k_build<<<NPIX / 2048, 256>>>((const float4*)x, lbl);
    for (int c = 0; c < CNUM; c++) {
        k_compute<<<2816, 256>>>(c, index, w1, b1, w2, b2);
        k_scatter<<<2816, 256>>>(c);
    }
    k_final<<<NPIX / 1024, 256>>>((float4*)d_out);
}

// round 10
// speedup vs baseline: 1.6334x; 1.3671x over previous
#include <cuda_runtime.h>
#include <cstdint>
#include <cstddef>

#define BN 16
#define HH 512
#define WW 512
#define NPIX (BN*HH*WW)          // 4194304
#define CNUM 6
#define LNUM 3
#define RINGN 2044               // ring pixels per sample
#define SCAT_BLK 2816

// ---------------- static device scratch (no allocations allowed) ----------------
__device__ float    g_img[NPIX];                     // normalized working image (16MB)
__device__ float    g_cvals[NPIX];                   // per-class staged c values (16MB)
__device__ unsigned g_list[(size_t)CNUM * NPIX];     // per-class interior pixel lists
__device__ unsigned g_cnt[CNUM];
__device__ unsigned g_mnu[BN], g_mxu[BN];            // order-encoded min/max bits
__device__ float    g_tbl[BN * CNUM * 128];          // per (b,cls): 25*float4 weights,
                                                     // float4 biases, 3*float4 bezier params
__device__ float    g_ring[BN * RINGN];              // staged border results

// ---------------- helpers ----------------
__device__ __forceinline__ unsigned fenc(float f) {
    unsigned b = __float_as_uint(f);
    return (b & 0x80000000u) ? ~b : (b | 0x80000000u);
}
__device__ __forceinline__ float fdec(unsigned u) {
    unsigned b = (u & 0x80000000u) ? (u ^ 0x80000000u) : ~u;
    return __uint_as_float(b);
}
__device__ __forceinline__ float sigm(float x) { return 1.0f / (1.0f + __expf(-x)); }

__device__ __forceinline__ float bez(float c, float mix,
                                     float p1, float p2, float p1v, float p2v) {
    float om  = 1.0f - c;
    float om2 = om * om, c2 = c * c;
    float ct = 3.0f * om2 * c * p1 + 3.0f * om * c2 * p2 + c2 * c;
    float cv = om2 * om + 3.0f * om2 * c * p1v + 3.0f * om * c2 * p2v;
    float v  = ct * mix + cv * (1.0f - mix);
    return fminf(fmaxf(v, 0.0f), 1.0f);
}

__device__ __forceinline__ void ring_yx(int q, int& y, int& x) {
    if (q < 512)       { y = 0;   x = q; }
    else if (q < 1024) { y = 511; x = q - 512; }
    else if (q < 1534) { x = 0;   y = q - 1023; }
    else               { x = 511; y = q - 1533; }
}

// ---------------- setup: counters/minmax init + effective 5x5 table ----------------
__global__ void k_setup(const int* __restrict__ index, const float* __restrict__ param,
                        const float* __restrict__ w1, const float* __restrict__ b1,
                        const float* __restrict__ w2, const float* __restrict__ b2) {
    int t = threadIdx.x;
    if (t < CNUM) g_cnt[t] = 0u;
    if (t < BN) { g_mnu[t] = 0xFFFFFFFFu; g_mxu[t] = 0u; }
    if (t >= BN * CNUM * LNUM) return;
    int b = t / (CNUM * LNUM);
    int i = (t / LNUM) % CNUM;
    int l = t % LNUM;
    int d = __ldg(index + b);
    int k = ((d * CNUM + i) * 4) * LNUM + l;   // aug index fixed to 0
    const float* W1 = w1 + (size_t)k * 36;
    const float* W2 = w2 + (size_t)k * 36;
    const float* B1 = b1 + (size_t)k * 4;
    const float* P  = param + (size_t)k * 7;

    float wef[25];
#pragma unroll
    for (int j = 0; j < 25; j++) wef[j] = 0.0f;
    float beff = __ldg(b2 + k);
#pragma unroll
    for (int ch = 0; ch < 4; ch++) {
        float s2 = 0.0f;
#pragma unroll
        for (int e = 0; e < 9; e++) {
            float w2v = __ldg(W2 + ch * 9 + e);
            s2 += w2v;
            int ey = e / 3, ex = e % 3;
#pragma unroll
            for (int dd = 0; dd < 9; dd++) {
                wef[(ey + dd / 3) * 5 + (ex + dd % 3)] += w2v * __ldg(W1 + ch * 9 + dd);
            }
        }
        beff += __ldg(B1 + ch) * s2;
    }
    float* T = g_tbl + (size_t)(b * CNUM + i) * 128;
#pragma unroll
    for (int j = 0; j < 25; j++) T[j * 4 + l] = wef[j];
    T[100 + l] = beff;
#pragma unroll
    for (int j = 0; j < 4; j++) T[104 + l * 4 + j] = sigm(__ldg(P + j));
    if (l == 0) {
        T[103] = 0.0f;
#pragma unroll
        for (int j = 0; j < 25; j++) T[j * 4 + 3] = 0.0f;
    }
}

// per-sample min/max
__global__ void k_minmax(const float4* __restrict__ x) {
    int b = blockIdx.x >> 3, chunk = blockIdx.x & 7;
    const float4* p = x + (size_t)b * 65536 + (size_t)chunk * 8192;
    float mn = 3.4e38f, mx = -3.4e38f;
    for (int i = threadIdx.x; i < 8192; i += 256) {
        float4 v = __ldg(p + i);
        mn = fminf(mn, fminf(fminf(v.x, v.y), fminf(v.z, v.w)));
        mx = fmaxf(mx, fmaxf(fmaxf(v.x, v.y), fmaxf(v.z, v.w)));
    }
    for (int o = 16; o; o >>= 1) {
        mn = fminf(mn, __shfl_down_sync(0xffffffffu, mn, o));
        mx = fmaxf(mx, __shfl_down_sync(0xffffffffu, mx, o));
    }
    __shared__ float smn[8], smx[8];
    if ((threadIdx.x & 31) == 0) { smn[threadIdx.x >> 5] = mn; smx[threadIdx.x >> 5] = mx; }
    __syncthreads();
    if (threadIdx.x == 0) {
        for (int w = 1; w < 8; w++) { mn = fminf(mn, smn[w]); mx = fmaxf(mx, smx[w]); }
        atomicMin(&g_mnu[b], fenc(mn));
        atomicMax(&g_mxu[b], fenc(mx));
    }
}

// Fused normalize + per-class INTERIOR pixel list build (ring pixels excluded,
// handled by k_border). Atomic-free emission.
__global__ void __launch_bounds__(256) k_build(const float4* __restrict__ x,
                                               const int* __restrict__ lbl) {
    __shared__ unsigned scur[CNUM];
    __shared__ unsigned sbase[CNUM];
    const int t = threadIdx.x;
    const int lane = t & 31;
    const unsigned base = blockIdx.x * 2048u;
    const int b = base >> 18;

    // fused normalization: 2 float4 per thread
    {
        float mn  = fdec(g_mnu[b]);
        float inv = 1.0f / (fdec(g_mxu[b]) - mn + 1e-8f);
        unsigned f4 = (base >> 2) + t;
#pragma unroll
        for (int s = 0; s < 2; s++) {
            float4 v = __ldg(x + f4 + s * 256);
            reinterpret_cast<float4*>(g_img)[f4 + s * 256] =
                make_float4((v.x - mn) * inv, (v.y - mn) * inv,
                            (v.z - mn) * inv, (v.w - mn) * inv);
        }
    }

    if (t < CNUM) scur[t] = 0u;
    __syncthreads();

    // pass A: counts (interior only), labels stashed
    int lc[8];
    unsigned c0 = 0, c1 = 0, c2 = 0, c3 = 0, c4 = 0, c5 = 0;
#pragma unroll
    for (int s = 0; s < 8; s++) {
        unsigned p = base + (unsigned)s * 256u + t;
        int c = __ldg(lbl + p);
        unsigned yy = (p >> 9) & 511u, xx = p & 511u;
        if (!((yy - 1u) < 510u && (xx - 1u) < 510u)) c = 6;   // ring -> excluded
        lc[s] = c;
        c0 += (c == 0); c1 += (c == 1); c2 += (c == 2);
        c3 += (c == 3); c4 += (c == 4); c5 += (c == 5);
    }
#pragma unroll
    for (int o = 16; o; o >>= 1) {
        c0 += __shfl_down_sync(0xffffffffu, c0, o);
        c1 += __shfl_down_sync(0xffffffffu, c1, o);
        c2 += __shfl_down_sync(0xffffffffu, c2, o);
        c3 += __shfl_down_sync(0xffffffffu, c3, o);
        c4 += __shfl_down_sync(0xffffffffu, c4, o);
        c5 += __shfl_down_sync(0xffffffffu, c5, o);
    }
    unsigned w0 = 0, w1o = 0, w2o = 0, w3o = 0, w4o = 0, w5o = 0;
    if (lane == 0) {
        w0  = atomicAdd(&scur[0], c0); w1o = atomicAdd(&scur[1], c1);
        w2o = atomicAdd(&scur[2], c2); w3o = atomicAdd(&scur[3], c3);
        w4o = atomicAdd(&scur[4], c4); w5o = atomicAdd(&scur[5], c5);
    }
    __syncthreads();
    if (t < CNUM) sbase[t] = atomicAdd(&g_cnt[t], scur[t]);
    __syncthreads();
    unsigned r0 = sbase[0] + __shfl_sync(0xffffffffu, w0, 0);
    unsigned r1 = sbase[1] + __shfl_sync(0xffffffffu, w1o, 0);
    unsigned r2 = sbase[2] + __shfl_sync(0xffffffffu, w2o, 0);
    unsigned r3 = sbase[3] + __shfl_sync(0xffffffffu, w3o, 0);
    unsigned r4 = sbase[4] + __shfl_sync(0xffffffffu, w4o, 0);
    unsigned r5 = sbase[5] + __shfl_sync(0xffffffffu, w5o, 0);
    const unsigned lmask = (1u << lane) - 1u;

    // pass B: atomic-free emit
#pragma unroll
    for (int s = 0; s < 8; s++) {
        unsigned p = base + (unsigned)s * 256u + t;
        int myc = lc[s];
        unsigned m;
        m = __ballot_sync(0xffffffffu, myc == 0);
        if (myc == 0) g_list[0 * (size_t)NPIX + r0 + __popc(m & lmask)] = p;
        r0 += __popc(m);
        m = __ballot_sync(0xffffffffu, myc == 1);
        if (myc == 1) g_list[1 * (size_t)NPIX + r1 + __popc(m & lmask)] = p;
        r1 += __popc(m);
        m = __ballot_sync(0xffffffffu, myc == 2);
        if (myc == 2) g_list[2 * (size_t)NPIX + r2 + __popc(m & lmask)] = p;
        r2 += __popc(m);
        m = __ballot_sync(0xffffffffu, myc == 3);
        if (myc == 3) g_list[3 * (size_t)NPIX + r3 + __popc(m & lmask)] = p;
        r3 += __popc(m);
        m = __ballot_sync(0xffffffffu, myc == 4);
        if (myc == 4) g_list[4 * (size_t)NPIX + r4 + __popc(m & lmask)] = p;
        r4 += __popc(m);
        m = __ballot_sync(0xffffffffu, myc == 5);
        if (myc == 5) g_list[5 * (size_t)NPIX + r5 + __popc(m & lmask)] = p;
        r5 += __popc(m);
    }
}

// Interior-only per-class compute: slim composed 5x5 path, direct accumulation,
// 64-reg cap for occupancy.
__global__ void __launch_bounds__(256, 4) k_compute(int cls) {
    __shared__ float4 sT[BN * 32];   // 8KB
    {
        const float4* gT = reinterpret_cast<const float4*>(g_tbl);
#pragma unroll
        for (int s = 0; s < 2; s++) {
            int i = threadIdx.x + s * 256;
            sT[i] = __ldg(gT + (size_t)((i >> 5) * CNUM + cls) * 32 + (i & 31));
        }
    }
    __syncthreads();

    unsigned cnt = g_cnt[cls];
    const unsigned* __restrict__ list = g_list + (size_t)cls * NPIX;
    unsigned stride = gridDim.x * blockDim.x;
    for (unsigned j = blockIdx.x * 256u + threadIdx.x; j < cnt; j += stride) {
        unsigned p = __ldg(list + j);
        int b = p >> 18;
        int y = (p >> 9) & 511;
        int x = p & 511;
        const float4* T4 = sT + (b << 5);
        float4 bb4 = T4[25];
        float a0 = bb4.x, a1 = bb4.y, a2 = bb4.z;
        float cc = 0.0f;

        if (y >= 2 && y < 510 && x >= 2 && x < 510) {
            const float* q = g_img + p - 2 * WW - 2;
#pragma unroll
            for (int t = 0; t < 25; t++) {
                float v = __ldg(q + (t / 5) * WW + (t % 5));
                float4 w = T4[t];
                a0 += v * w.x; a1 += v * w.y; a2 += v * w.z;
                if (t == 12) cc = v;
            }
        } else {
            const float* basep = g_img + ((size_t)b << 18);
#pragma unroll
            for (int t = 0; t < 25; t++) {
                int yy = y + t / 5 - 2, xx = x + t % 5 - 2;
                float v = (yy >= 0 && yy < HH && xx >= 0 && xx < WW)
                          ? __ldg(basep + yy * WW + xx) : 0.0f;
                float4 w = T4[t];
                a0 += v * w.x; a1 += v * w.y; a2 += v * w.z;
                if (t == 12) cc = v;
            }
        }
        float4 pA = T4[26], pB = T4[27], pC = T4[28];
        cc = bez(cc, sigm(a0), pA.x, pA.y, pA.z, pA.w);
        cc = bez(cc, sigm(a1), pB.x, pB.y, pB.z, pB.w);
        cc = bez(cc, sigm(a2), pC.x, pC.y, pC.z, pC.w);
        g_cvals[j] = cc;
    }
}

// Border ring: exact two-step conv (intermediate h zero-padded), staged to g_ring.
__global__ void k_border(int cls, const int* __restrict__ lbl,
                         const int* __restrict__ index,
                         const float* __restrict__ w1, const float* __restrict__ b1,
                         const float* __restrict__ w2, const float* __restrict__ b2) {
    int r = blockIdx.x * 256 + threadIdx.x;
    if (r >= BN * RINGN) return;
    int b = r / RINGN, q = r % RINGN;
    int y, x;
    ring_yx(q, y, x);
    unsigned p = ((unsigned)b << 18) | ((unsigned)y << 9) | (unsigned)x;
    if (__ldg(lbl + p) != cls) return;

    const float* basep = g_img + ((size_t)b << 18);
    float nb[25];
#pragma unroll
    for (int t = 0; t < 25; t++) {
        int yy = y + t / 5 - 2, xx = x + t % 5 - 2;
        nb[t] = (yy >= 0 && yy < HH && xx >= 0 && xx < WW)
                ? __ldg(basep + yy * WW + xx) : 0.0f;
    }
    float cc = nb[12];
    int d = __ldg(index + b);
    int kb = ((d * CNUM + cls) * 4) * LNUM;
    const float* T = g_tbl + (size_t)(b * CNUM + cls) * 128;
#pragma unroll
    for (int l = 0; l < LNUM; l++) {
        int k = kb + l;
        const float* W1 = w1 + (size_t)k * 36;
        const float* W2 = w2 + (size_t)k * 36;
        const float* B1 = b1 + (size_t)k * 4;
        float acc = __ldg(b2 + k);
#pragma unroll
        for (int e = 0; e < 9; e++) {
            int ey = e / 3 - 1, ex = e % 3 - 1;
            int qy = y + ey, qx = x + ex;
            if (qy < 0 || qy >= HH || qx < 0 || qx >= WW) continue;
            float hs = 0.0f;
#pragma unroll
            for (int ch = 0; ch < 4; ch++) {
                float h = __ldg(B1 + ch);
#pragma unroll
                for (int dd = 0; dd < 9; dd++) {
                    int dy = dd / 3 - 1, dx = dd % 3 - 1;
                    h += __ldg(W1 + ch * 9 + dd) * nb[(2 + ey + dy) * 5 + (2 + ex + dx)];
                }
                hs += h * __ldg(W2 + ch * 9 + e);
            }
            acc += hs;
        }
        cc = bez(cc, sigm(acc), T[104 + l * 4], T[105 + l * 4],
                 T[106 + l * 4], T[107 + l * 4]);
    }
    g_ring[r] = cc;
}

// scatter staged values into image (list + ring tail blocks)
__global__ void k_scatter(int cls, const int* __restrict__ lbl) {
    if (blockIdx.x < SCAT_BLK) {
        unsigned cnt = g_cnt[cls];
        const unsigned* __restrict__ list = g_list + (size_t)cls * NPIX;
        unsigned stride = SCAT_BLK * 256u;
        for (unsigned j = blockIdx.x * 256u + threadIdx.x; j < cnt; j += stride)
            g_img[__ldg(list + j)] = __ldg(g_cvals + j);
    } else {
        int r = (blockIdx.x - SCAT_BLK) * 256 + threadIdx.x;
        if (r >= BN * RINGN) return;
        int b = r / RINGN, q = r % RINGN;
        int y, x;
        ring_yx(q, y, x);
        unsigned p = ((unsigned)b << 18) | ((unsigned)y << 9) | (unsigned)x;
        if (__ldg(lbl + p) == cls) g_img[p] = __ldg(g_ring + r);
    }
}

// denormalize into output
__global__ void k_final(float4* __restrict__ out) {
    unsigned i = blockIdx.x * 256u + threadIdx.x;
    int b = i >> 16;
    float mn = fdec(g_mnu[b]);
    float sc = fdec(g_mxu[b]) - mn + 1e-8f;
    float4 v = reinterpret_cast<const float4*>(g_img)[i];
    out[i] = make_float4(v.x * sc + mn, v.y * sc + mn, v.z * sc + mn, v.w * sc + mn);
}

// ---------------- launch ----------------
extern "C" void kernel_launch(void* const* d_in, const int* in_sizes, int n_in,
                              void* d_out, int out_size) {
    const float* x     = (const float*)d_in[0];
    const int*   lbl   = (const int*)d_in[1];
    const int*   index = (const int*)d_in[2];
    const float* param = (const float*)d_in[3];
    const float* w1    = (const float*)d_in[4];
    const float* b1    = (const float*)d_in[5];
    const float* w2    = (const float*)d_in[6];
    const float* b2    = (const float*)d_in[7];

    k_setup<<<1, 288>>>(index, param, w1, b1, w2, b2);
    k_minmax<<<BN * 8, 256>>>((const float4*)x);
    k_build<<<NPIX / 2048, 256>>>((const float4*)x, lbl);
    const int ringBlocks = (BN * RINGN + 255) / 256;  // 128
    for (int c = 0; c < CNUM; c++) {
        k_compute<<<2816, 256>>>(c);
        k_border<<<ringBlocks, 256>>>(c, lbl, index, w1, b1, w2, b2);
        k_scatter<<<SCAT_BLK + ringBlocks, 256>>>(c, lbl);
    }
    k_final<<<NPIX / 1024, 256>>>((float4*)d_out);
}

// round 11
// speedup vs baseline: 1.7311x; 1.0598x over previous
#include <cuda_runtime.h>
#include <cstdint>
#include <cstddef>

#define BN 16
#define HH 512
#define WW 512
#define NPIX (BN*HH*WW)          // 4194304
#define CNUM 6
#define LNUM 3
#define RINGN 2044               // ring pixels per sample
#define SCAT_BLK 2816
#define NTILE 2048               // 2048-pixel tiles (4 rows x 512), 128 per sample

// ---------------- static device scratch (no allocations allowed) ----------------
__device__ float    g_img[NPIX];                     // normalized working image (16MB)
__device__ float    g_cvals[NPIX];                   // per-class staged c values (16MB)
__device__ unsigned g_list[(size_t)CNUM * NPIX];     // per-class interior pixel lists
__device__ unsigned g_cnt[CNUM];
__device__ unsigned g_toff[CNUM * NTILE];            // CSR: start of (cls,tile) in list
__device__ unsigned g_tcnt[CNUM * NTILE];            // CSR: count
__device__ unsigned g_mnu[BN], g_mxu[BN];            // order-encoded min/max bits
__device__ float    g_tbl[BN * CNUM * 128];          // per (b,cls): 25*float4 weights,
                                                     // float4 biases, 3*float4 bezier params
__device__ float    g_ring[BN * RINGN];              // staged border results

// ---------------- helpers ----------------
__device__ __forceinline__ unsigned fenc(float f) {
    unsigned b = __float_as_uint(f);
    return (b & 0x80000000u) ? ~b : (b | 0x80000000u);
}
__device__ __forceinline__ float fdec(unsigned u) {
    unsigned b = (u & 0x80000000u) ? (u ^ 0x80000000u) : ~u;
    return __uint_as_float(b);
}
__device__ __forceinline__ float sigm(float x) { return 1.0f / (1.0f + __expf(-x)); }

__device__ __forceinline__ float bez(float c, float mix,
                                     float p1, float p2, float p1v, float p2v) {
    float om  = 1.0f - c;
    float om2 = om * om, c2 = c * c;
    float ct = 3.0f * om2 * c * p1 + 3.0f * om * c2 * p2 + c2 * c;
    float cv = om2 * om + 3.0f * om2 * c * p1v + 3.0f * om * c2 * p2v;
    float v  = ct * mix + cv * (1.0f - mix);
    return fminf(fmaxf(v, 0.0f), 1.0f);
}

__device__ __forceinline__ void ring_yx(int q, int& y, int& x) {
    if (q < 512)       { y = 0;   x = q; }
    else if (q < 1024) { y = 511; x = q - 512; }
    else if (q < 1534) { x = 0;   y = q - 1023; }
    else               { x = 511; y = q - 1533; }
}

// ---------------- setup: counters/minmax init + effective 5x5 table ----------------
__global__ void k_setup(const int* __restrict__ index, const float* __restrict__ param,
                        const float* __restrict__ w1, const float* __restrict__ b1,
                        const float* __restrict__ w2, const float* __restrict__ b2) {
    int t = threadIdx.x;
    if (t < CNUM) g_cnt[t] = 0u;
    if (t < BN) { g_mnu[t] = 0xFFFFFFFFu; g_mxu[t] = 0u; }
    if (t >= BN * CNUM * LNUM) return;
    int b = t / (CNUM * LNUM);
    int i = (t / LNUM) % CNUM;
    int l = t % LNUM;
    int d = __ldg(index + b);
    int k = ((d * CNUM + i) * 4) * LNUM + l;   // aug index fixed to 0
    const float* W1 = w1 + (size_t)k * 36;
    const float* W2 = w2 + (size_t)k * 36;
    const float* B1 = b1 + (size_t)k * 4;
    const float* P  = param + (size_t)k * 7;

    float wef[25];
#pragma unroll
    for (int j = 0; j < 25; j++) wef[j] = 0.0f;
    float beff = __ldg(b2 + k);
#pragma unroll
    for (int ch = 0; ch < 4; ch++) {
        float s2 = 0.0f;
#pragma unroll
        for (int e = 0; e < 9; e++) {
            float w2v = __ldg(W2 + ch * 9 + e);
            s2 += w2v;
            int ey = e / 3, ex = e % 3;
#pragma unroll
            for (int dd = 0; dd < 9; dd++) {
                wef[(ey + dd / 3) * 5 + (ex + dd % 3)] += w2v * __ldg(W1 + ch * 9 + dd);
            }
        }
        beff += __ldg(B1 + ch) * s2;
    }
    float* T = g_tbl + (size_t)(b * CNUM + i) * 128;
#pragma unroll
    for (int j = 0; j < 25; j++) T[j * 4 + l] = wef[j];
    T[100 + l] = beff;
#pragma unroll
    for (int j = 0; j < 4; j++) T[104 + l * 4 + j] = sigm(__ldg(P + j));
    if (l == 0) {
        T[103] = 0.0f;
#pragma unroll
        for (int j = 0; j < 25; j++) T[j * 4 + 3] = 0.0f;
    }
}

// per-sample min/max
__global__ void k_minmax(const float4* __restrict__ x) {
    int b = blockIdx.x >> 3, chunk = blockIdx.x & 7;
    const float4* p = x + (size_t)b * 65536 + (size_t)chunk * 8192;
    float mn = 3.4e38f, mx = -3.4e38f;
    for (int i = threadIdx.x; i < 8192; i += 256) {
        float4 v = __ldg(p + i);
        mn = fminf(mn, fminf(fminf(v.x, v.y), fminf(v.z, v.w)));
        mx = fmaxf(mx, fmaxf(fmaxf(v.x, v.y), fmaxf(v.z, v.w)));
    }
    for (int o = 16; o; o >>= 1) {
        mn = fminf(mn, __shfl_down_sync(0xffffffffu, mn, o));
        mx = fmaxf(mx, __shfl_down_sync(0xffffffffu, mx, o));
    }
    __shared__ float smn[8], smx[8];
    if ((threadIdx.x & 31) == 0) { smn[threadIdx.x >> 5] = mn; smx[threadIdx.x >> 5] = mx; }
    __syncthreads();
    if (threadIdx.x == 0) {
        for (int w = 1; w < 8; w++) { mn = fminf(mn, smn[w]); mx = fmaxf(mx, smx[w]); }
        atomicMin(&g_mnu[b], fenc(mn));
        atomicMax(&g_mxu[b], fenc(mx));
    }
}

// Fused normalize + per-class INTERIOR pixel list build (ring excluded) +
// per-(class,tile) CSR record. Block == tile (2048 consecutive pixels).
__global__ void __launch_bounds__(256) k_build(const float4* __restrict__ x,
                                               const int* __restrict__ lbl) {
    __shared__ unsigned scur[CNUM];
    __shared__ unsigned sbase[CNUM];
    const int t = threadIdx.x;
    const int lane = t & 31;
    const unsigned base = blockIdx.x * 2048u;
    const int b = base >> 18;

    // fused normalization: 2 float4 per thread
    {
        float mn  = fdec(g_mnu[b]);
        float inv = 1.0f / (fdec(g_mxu[b]) - mn + 1e-8f);
        unsigned f4 = (base >> 2) + t;
#pragma unroll
        for (int s = 0; s < 2; s++) {
            float4 v = __ldg(x + f4 + s * 256);
            reinterpret_cast<float4*>(g_img)[f4 + s * 256] =
                make_float4((v.x - mn) * inv, (v.y - mn) * inv,
                            (v.z - mn) * inv, (v.w - mn) * inv);
        }
    }

    if (t < CNUM) scur[t] = 0u;
    __syncthreads();

    // pass A: counts (interior only), labels stashed
    int lc[8];
    unsigned c0 = 0, c1 = 0, c2 = 0, c3 = 0, c4 = 0, c5 = 0;
#pragma unroll
    for (int s = 0; s < 8; s++) {
        unsigned p = base + (unsigned)s * 256u + t;
        int c = __ldg(lbl + p);
        unsigned yy = (p >> 9) & 511u, xx = p & 511u;
        if (!((yy - 1u) < 510u && (xx - 1u) < 510u)) c = 6;   // ring -> excluded
        lc[s] = c;
        c0 += (c == 0); c1 += (c == 1); c2 += (c == 2);
        c3 += (c == 3); c4 += (c == 4); c5 += (c == 5);
    }
#pragma unroll
    for (int o = 16; o; o >>= 1) {
        c0 += __shfl_down_sync(0xffffffffu, c0, o);
        c1 += __shfl_down_sync(0xffffffffu, c1, o);
        c2 += __shfl_down_sync(0xffffffffu, c2, o);
        c3 += __shfl_down_sync(0xffffffffu, c3, o);
        c4 += __shfl_down_sync(0xffffffffu, c4, o);
        c5 += __shfl_down_sync(0xffffffffu, c5, o);
    }
    unsigned w0 = 0, w1o = 0, w2o = 0, w3o = 0, w4o = 0, w5o = 0;
    if (lane == 0) {
        w0  = atomicAdd(&scur[0], c0); w1o = atomicAdd(&scur[1], c1);
        w2o = atomicAdd(&scur[2], c2); w3o = atomicAdd(&scur[3], c3);
        w4o = atomicAdd(&scur[4], c4); w5o = atomicAdd(&scur[5], c5);
    }
    __syncthreads();
    if (t < CNUM) {
        unsigned tot = scur[t];
        unsigned gb = atomicAdd(&g_cnt[t], tot);
        sbase[t] = gb;
        g_toff[t * NTILE + blockIdx.x] = gb;    // CSR for tiled compute
        g_tcnt[t * NTILE + blockIdx.x] = tot;
    }
    __syncthreads();
    unsigned r0 = sbase[0] + __shfl_sync(0xffffffffu, w0, 0);
    unsigned r1 = sbase[1] + __shfl_sync(0xffffffffu, w1o, 0);
    unsigned r2 = sbase[2] + __shfl_sync(0xffffffffu, w2o, 0);
    unsigned r3 = sbase[3] + __shfl_sync(0xffffffffu, w3o, 0);
    unsigned r4 = sbase[4] + __shfl_sync(0xffffffffu, w4o, 0);
    unsigned r5 = sbase[5] + __shfl_sync(0xffffffffu, w5o, 0);
    const unsigned lmask = (1u << lane) - 1u;

    // pass B: atomic-free emit
#pragma unroll
    for (int s = 0; s < 8; s++) {
        unsigned p = base + (unsigned)s * 256u + t;
        int myc = lc[s];
        unsigned m;
        m = __ballot_sync(0xffffffffu, myc == 0);
        if (myc == 0) g_list[0 * (size_t)NPIX + r0 + __popc(m & lmask)] = p;
        r0 += __popc(m);
        m = __ballot_sync(0xffffffffu, myc == 1);
        if (myc == 1) g_list[1 * (size_t)NPIX + r1 + __popc(m & lmask)] = p;
        r1 += __popc(m);
        m = __ballot_sync(0xffffffffu, myc == 2);
        if (myc == 2) g_list[2 * (size_t)NPIX + r2 + __popc(m & lmask)] = p;
        r2 += __popc(m);
        m = __ballot_sync(0xffffffffu, myc == 3);
        if (myc == 3) g_list[3 * (size_t)NPIX + r3 + __popc(m & lmask)] = p;
        r3 += __popc(m);
        m = __ballot_sync(0xffffffffu, myc == 4);
        if (myc == 4) g_list[4 * (size_t)NPIX + r4 + __popc(m & lmask)] = p;
        r4 += __popc(m);
        m = __ballot_sync(0xffffffffu, myc == 5);
        if (myc == 5) g_list[5 * (size_t)NPIX + r5 + __popc(m & lmask)] = p;
        r5 += __popc(m);
    }
}

// Tiled interior compute: one block per 4x512 tile. Coalesced halo load into
// zero-padded smem, then per-pixel 5x5 gathers from LDS (no bounds branches).
__global__ void __launch_bounds__(256) k_compute(int cls) {
    __shared__ float  srow[8][516];       // rows y0-2..y0+5, cols pad:2 +512+ pad:2
    __shared__ float4 sW[32];             // this (sample, cls) table

    const int tile = blockIdx.x;
    const unsigned cnt = g_tcnt[cls * NTILE + tile];
    if (cnt == 0) return;
    const int b  = tile >> 7;
    const int y0 = (tile & 127) << 2;

    // coalesced halo load: 8 rows x 128 float4
    const float4* img4 = reinterpret_cast<const float4*>(g_img) + (size_t)b * 65536;
#pragma unroll
    for (int k = 0; k < 4; k++) {
        int idx = threadIdx.x + k * 256;      // 0..1023
        int r = idx >> 7, xq = idx & 127;
        int y = y0 - 2 + r;
        float4 v = (y >= 0 && y < HH) ? __ldg(img4 + y * 128 + xq)
                                      : make_float4(0.f, 0.f, 0.f, 0.f);
        float* dst = &srow[r][2 + xq * 4];
        dst[0] = v.x; dst[1] = v.y; dst[2] = v.z; dst[3] = v.w;
    }
    if (threadIdx.x < 8) {
        srow[threadIdx.x][0] = 0.f;   srow[threadIdx.x][1] = 0.f;
        srow[threadIdx.x][514] = 0.f; srow[threadIdx.x][515] = 0.f;
    }
    if (threadIdx.x < 32)
        sW[threadIdx.x] = __ldg(reinterpret_cast<const float4*>(g_tbl)
                                + (size_t)(b * CNUM + cls) * 32 + threadIdx.x);
    __syncthreads();

    const unsigned off = g_toff[cls * NTILE + tile];
    const unsigned* __restrict__ list = g_list + (size_t)cls * NPIX;
    for (unsigned j = off + threadIdx.x; j < off + cnt; j += 256) {
        unsigned p = __ldg(list + j);
        int lx = (int)(p & 511u) + 2;
        int ly = (int)((p >> 9) & 511u) - y0 + 2;   // 2..5

        float4 bb4 = sW[25];
        float a0 = bb4.x, a1 = bb4.y, a2 = bb4.z;
#pragma unroll
        for (int r = 0; r < 5; r++) {
            const float* row = &srow[ly - 2 + r][lx - 2];
#pragma unroll
            for (int cix = 0; cix < 5; cix++) {
                float v = row[cix];
                float4 w = sW[r * 5 + cix];
                a0 += v * w.x; a1 += v * w.y; a2 += v * w.z;
            }
        }
        float cc = srow[ly][lx];
        float4 pA = sW[26], pB = sW[27], pC = sW[28];
        cc = bez(cc, sigm(a0), pA.x, pA.y, pA.z, pA.w);
        cc = bez(cc, sigm(a1), pB.x, pB.y, pB.z, pB.w);
        cc = bez(cc, sigm(a2), pC.x, pC.y, pC.z, pC.w);
        g_cvals[j] = cc;
    }
}

// Border ring: exact two-step conv (intermediate h zero-padded), staged to g_ring.
__global__ void k_border(int cls, const int* __restrict__ lbl,
                         const int* __restrict__ index,
                         const float* __restrict__ w1, const float* __restrict__ b1,
                         const float* __restrict__ w2, const float* __restrict__ b2) {
    int r = blockIdx.x * 256 + threadIdx.x;
    if (r >= BN * RINGN) return;
    int b = r / RINGN, q = r % RINGN;
    int y, x;
    ring_yx(q, y, x);
    unsigned p = ((unsigned)b << 18) | ((unsigned)y << 9) | (unsigned)x;
    if (__ldg(lbl + p) != cls) return;

    const float* basep = g_img + ((size_t)b << 18);
    float nb[25];
#pragma unroll
    for (int t = 0; t < 25; t++) {
        int yy = y + t / 5 - 2, xx = x + t % 5 - 2;
        nb[t] = (yy >= 0 && yy < HH && xx >= 0 && xx < WW)
                ? __ldg(basep + yy * WW + xx) : 0.0f;
    }
    float cc = nb[12];
    int d = __ldg(index + b);
    int kb = ((d * CNUM + cls) * 4) * LNUM;
    const float* T = g_tbl + (size_t)(b * CNUM + cls) * 128;
#pragma unroll
    for (int l = 0; l < LNUM; l++) {
        int k = kb + l;
        const float* W1 = w1 + (size_t)k * 36;
        const float* W2 = w2 + (size_t)k * 36;
        const float* B1 = b1 + (size_t)k * 4;
        float acc = __ldg(b2 + k);
#pragma unroll
        for (int e = 0; e < 9; e++) {
            int ey = e / 3 - 1, ex = e % 3 - 1;
            int qy = y + ey, qx = x + ex;
            if (qy < 0 || qy >= HH || qx < 0 || qx >= WW) continue;
            float hs = 0.0f;
#pragma unroll
            for (int ch = 0; ch < 4; ch++) {
                float h = __ldg(B1 + ch);
#pragma unroll
                for (int dd = 0; dd < 9; dd++) {
                    int dy = dd / 3 - 1, dx = dd % 3 - 1;
                    h += __ldg(W1 + ch * 9 + dd) * nb[(2 + ey + dy) * 5 + (2 + ex + dx)];
                }
                hs += h * __ldg(W2 + ch * 9 + e);
            }
            acc += hs;
        }
        cc = bez(cc, sigm(acc), T[104 + l * 4], T[105 + l * 4],
                 T[106 + l * 4], T[107 + l * 4]);
    }
    g_ring[r] = cc;
}

// scatter staged values into image (list + ring tail blocks)
__global__ void k_scatter(int cls, const int* __restrict__ lbl) {
    if (blockIdx.x < SCAT_BLK) {
        unsigned cnt = g_cnt[cls];
        const unsigned* __restrict__ list = g_list + (size_t)cls * NPIX;
        unsigned stride = SCAT_BLK * 256u;
        for (unsigned j = blockIdx.x * 256u + threadIdx.x; j < cnt; j += stride)
            g_img[__ldg(list + j)] = __ldg(g_cvals + j);
    } else {
        int r = (blockIdx.x - SCAT_BLK) * 256 + threadIdx.x;
        if (r >= BN * RINGN) return;
        int b = r / RINGN, q = r % RINGN;
        int y, x;
        ring_yx(q, y, x);
        unsigned p = ((unsigned)b << 18) | ((unsigned)y << 9) | (unsigned)x;
        if (__ldg(lbl + p) == cls) g_img[p] = __ldg(g_ring + r);
    }
}

// denormalize into output
__global__ void k_final(float4* __restrict__ out) {
    unsigned i = blockIdx.x * 256u + threadIdx.x;
    int b = i >> 16;
    float mn = fdec(g_mnu[b]);
    float sc = fdec(g_mxu[b]) - mn + 1e-8f;
    float4 v = reinterpret_cast<const float4*>(g_img)[i];
    out[i] = make_float4(v.x * sc + mn, v.y * sc + mn, v.z * sc + mn, v.w * sc + mn);
}

// ---------------- launch ----------------
extern "C" void kernel_launch(void* const* d_in, const int* in_sizes, int n_in,
                              void* d_out, int out_size) {
    const float* x     = (const float*)d_in[0];
    const int*   lbl   = (const int*)d_in[1];
    const int*   index = (const int*)d_in[2];
    const float* param = (const float*)d_in[3];
    const float* w1    = (const float*)d_in[4];
    const float* b1    = (const float*)d_in[5];
    const float* w2    = (const float*)d_in[6];
    const float* b2    = (const float*)d_in[7];

    k_setup<<<1, 288>>>(index, param, w1, b1, w2, b2);
    k_minmax<<<BN * 8, 256>>>((const float4*)x);
    k_build<<<NTILE, 256>>>((const float4*)x, lbl);
    const int ringBlocks = (BN * RINGN + 255) / 256;  // 128
    for (int c = 0; c < CNUM; c++) {
        k_compute<<<NTILE, 256>>>(c);
        k_border<<<ringBlocks, 256>>>(c, lbl, index, w1, b1, w2, b2);
        k_scatter<<<SCAT_BLK + ringBlocks, 256>>>(c, lbl);
    }
    k_final<<<NPIX / 1024, 256>>>((float4*)d_out);
}